// round 7
// baseline (speedup 1.0000x reference)
#include <cuda_runtime.h>
#include <math.h>
#include <stdint.h>

#define VSZ 32000
#define ESZ 512
#define HSZ 1024
#define SSZ 64
#define TSZ 64
#define BSZ 32
#define HB  (HSZ*BSZ)          // 32768
#define PAD_IDX 1
#define NEGV -100000.0f

// ---------------- device scratch ----------------
__device__ float g_emb_src[SSZ*BSZ*ESZ];        // [m=(s,b)][e]
__device__ float g_emb_dec[TSZ*BSZ*ESZ];        // [m=(t,b)][e]
__device__ float g_gx_enc[SSZ*3*HSZ*BSZ];       // [s][n][b]  (+bih0)
__device__ float g_gx_dec[TSZ*3*HSZ*BSZ];       // [t][n][b]  (+bih0)
__device__ float g_enc_out_t[SSZ*BSZ*HSZ];      // [s][b][h]
__device__ float g_h0[2*HB];                    // [h][b], double buffered
__device__ float g_h1[2*HB];
__device__ float g_dh0[2*HB];
__device__ float g_dh1[2*HB];
__device__ float g_h1t[2*BSZ*HSZ];              // [buf][b][h] double buffered
__device__ float g_ctx_t[BSZ*HSZ];              // [b][h]
__device__ float g_cc_all[TSZ*BSZ*HSZ];         // [m=(t,b)][h], tf32-rounded
__device__ float g_wo_tf[VSZ*HSZ];              // Wo, tf32-rounded

// ---------------- helpers ----------------
__device__ __forceinline__ uint32_t f2tf32(float f) {
    uint32_t u;
    asm("cvt.rna.tf32.f32 %0, %1;" : "=r"(u) : "f"(f));
    return u;
}
__device__ __forceinline__ void cp16(uint32_t s, const void* g) {
    asm volatile("cp.async.cg.shared.global [%0], [%1], 16;" :: "r"(s), "l"(g));
}
#define CP_COMMIT() asm volatile("cp.async.commit_group;" ::: "memory")
#define CP_WAIT(N)  asm volatile("cp.async.wait_group %0;" :: "n"(N) : "memory")

__device__ __forceinline__ void mma_tf32(float* c, const uint32_t* a, const uint32_t* b) {
    asm volatile(
        "mma.sync.aligned.m16n8k8.row.col.f32.tf32.tf32.f32 "
        "{%0,%1,%2,%3},{%4,%5,%6,%7},{%8,%9},{%0,%1,%2,%3};"
        : "+f"(c[0]), "+f"(c[1]), "+f"(c[2]), "+f"(c[3])
        : "r"(a[0]), "r"(a[1]), "r"(a[2]), "r"(a[3]), "r"(b[0]), "r"(b[1]));
}

// ---------------- utility kernels ----------------
__global__ void zero_kernel(float* p, int n) {
    for (int i = blockIdx.x*blockDim.x + threadIdx.x; i < n; i += gridDim.x*blockDim.x)
        p[i] = 0.f;
}
__global__ void zero_h2_kernel(float* a, float* b) {
    int i = blockIdx.x*256 + threadIdx.x;
    if (i < HB) a[i] = 0.f; else b[i - HB] = 0.f;
}
__global__ void cvt_tf32_kernel(const float* __restrict__ in, float* __restrict__ out) {
    int i = blockIdx.x*256 + threadIdx.x;     // n/4 threads
    float4 v = ((const float4*)in)[i];
    uint4 u = make_uint4(f2tf32(v.x), f2tf32(v.y), f2tf32(v.z), f2tf32(v.w));
    ((uint4*)out)[i] = u;
}

// out[m][e] = emb[tok[m]][e]
__global__ void embed_kernel(const int* __restrict__ tok,
                             const float* __restrict__ emb,
                             float* __restrict__ out, int rows) {
    int idx = blockIdx.x*256 + threadIdx.x;
    if (idx >= rows*ESZ) return;
    int e = idx & (ESZ-1);
    int m = idx >> 9;
    out[idx] = emb[(size_t)tok[m]*ESZ + e];
}

// ---------------- input projection: gx[t][n][b] = W[n][:]·X[m][:] + bih[n] ----
__global__ __launch_bounds__(256) void proj_gemm(
    const float* __restrict__ X,   // [M][512]
    const float* __restrict__ W,   // [3072][512]
    const float* __restrict__ bih,
    float* __restrict__ gx)        // [t][n][b]
{
    __shared__ float Xs[2][16][64];
    __shared__ float Ws[2][16][64];
    int tid = threadIdx.x;
    int mb = blockIdx.x*64, nb = blockIdx.y*64;
    int lr = tid >> 2, lc = (tid & 3) * 4;
    const float* Xg = X + (size_t)(mb+lr)*ESZ + lc;
    const float* Wg = W + (size_t)(nb+lr)*ESZ + lc;
    int tm = (tid & 15) * 4, tn = (tid >> 4) * 4;

    float acc[16];
    #pragma unroll
    for (int i = 0; i < 16; i++) acc[i] = 0.f;

    float4 px = *(const float4*)Xg;
    float4 pw = *(const float4*)Wg;
    for (int c = 0; c < 32; c++) {
        int buf = c & 1;
        Xs[buf][lc+0][lr]=px.x; Xs[buf][lc+1][lr]=px.y; Xs[buf][lc+2][lr]=px.z; Xs[buf][lc+3][lr]=px.w;
        Ws[buf][lc+0][lr]=pw.x; Ws[buf][lc+1][lr]=pw.y; Ws[buf][lc+2][lr]=pw.z; Ws[buf][lc+3][lr]=pw.w;
        __syncthreads();
        if (c < 31) {
            px = *(const float4*)(Xg + (c+1)*16);
            pw = *(const float4*)(Wg + (c+1)*16);
        }
        #pragma unroll
        for (int kk = 0; kk < 16; kk++) {
            float4 av = *(const float4*)&Xs[buf][kk][tm];
            float4 wv = *(const float4*)&Ws[buf][kk][tn];
            acc[0]+=av.x*wv.x; acc[1]+=av.x*wv.y; acc[2]+=av.x*wv.z; acc[3]+=av.x*wv.w;
            acc[4]+=av.y*wv.x; acc[5]+=av.y*wv.y; acc[6]+=av.y*wv.z; acc[7]+=av.y*wv.w;
            acc[8]+=av.z*wv.x; acc[9]+=av.z*wv.y; acc[10]+=av.z*wv.z; acc[11]+=av.z*wv.w;
            acc[12]+=av.w*wv.x; acc[13]+=av.w*wv.y; acc[14]+=av.w*wv.z; acc[15]+=av.w*wv.w;
        }
        __syncthreads();
    }
    #pragma unroll
    for (int i = 0; i < 4; i++) {
        int m = mb + tm + i;
        int t = m >> 5, b = m & 31;
        #pragma unroll
        for (int j = 0; j < 4; j++) {
            int n = nb + tn + j;
            gx[(size_t)t*3*HSZ*BSZ + (size_t)n*BSZ + b] = acc[i*4+j] + bih[n];
        }
    }
}

// ---------------- fused GRU layer-0 step ----------------
__global__ __launch_bounds__(256) void gru_l0(
    const float* __restrict__ gx,     // [3H][B]
    const float* __restrict__ h_old,  // [H][B]
    const float* __restrict__ Whh,    // [3H][H]
    const float* __restrict__ bhh,
    float* __restrict__ h_new)
{
    __shared__ float X[2][128][36];
    __shared__ float R[4][3][32];
    int tid = threadIdx.x, w = tid >> 5, lane = tid & 31;
    int p = w & 3, hf = w >> 2;
    int j = blockIdx.x*4 + p;
    const float* wr = Whh + (size_t)j*HSZ          + hf*512;
    const float* wz = Whh + (size_t)(HSZ+j)*HSZ    + hf*512;
    const float* wn = Whh + (size_t)(2*HSZ+j)*HSZ  + hf*512;
    float ar=0.f, az=0.f, an=0.f;

    for (int i = 0; i < 4; i++) {
        __syncthreads();
        #pragma unroll
        for (int it = 0; it < 8; it++) {
            int r = (tid >> 3) + it*32;            // 0..255
            int h = r >> 7, kk = r & 127;
            int gk = h*512 + i*128 + kk;
            *(float4*)&X[h][kk][(tid & 7)*4] =
                *(const float4*)(h_old + (size_t)gk*BSZ + (tid & 7)*4);
        }
        __syncthreads();
        #pragma unroll
        for (int q = 0; q < 32; q++) {
            float4 r4 = *(const float4*)(wr + i*128 + q*4);
            float4 z4 = *(const float4*)(wz + i*128 + q*4);
            float4 n4 = *(const float4*)(wn + i*128 + q*4);
            float x0 = X[hf][q*4+0][lane], x1 = X[hf][q*4+1][lane];
            float x2 = X[hf][q*4+2][lane], x3 = X[hf][q*4+3][lane];
            ar += r4.x*x0 + r4.y*x1 + r4.z*x2 + r4.w*x3;
            az += z4.x*x0 + z4.y*x1 + z4.z*x2 + z4.w*x3;
            an += n4.x*x0 + n4.y*x1 + n4.z*x2 + n4.w*x3;
        }
    }
    if (hf == 1) { R[p][0][lane]=ar; R[p][1][lane]=az; R[p][2][lane]=an; }
    __syncthreads();
    if (hf == 0) {
        float ghr = ar + R[p][0][lane] + bhh[j];
        float ghz = az + R[p][1][lane] + bhh[HSZ+j];
        float ghn = an + R[p][2][lane] + bhh[2*HSZ+j];
        float gr = gx[(size_t)j*BSZ + lane]         + ghr;
        float gz = gx[(size_t)(HSZ+j)*BSZ + lane]   + ghz;
        float r = 1.f/(1.f + expf(-gr));
        float z = 1.f/(1.f + expf(-gz));
        float n = tanhf(gx[(size_t)(2*HSZ+j)*BSZ + lane] + r*ghn);
        float hp = h_old[(size_t)j*BSZ + lane];
        h_new[(size_t)j*BSZ + lane] = (1.f - z)*n + z*hp;
    }
}

// ---------------- fused GRU layer-1 step ----------------
// dynamic smem: X[2 src][2 half][64][36]
#define L1_SMEM (2*2*64*36*4)
__global__ __launch_bounds__(256) void gru_l1(
    const float* __restrict__ x0,     // [H][B]
    const float* __restrict__ h1o,    // [H][B]
    const float* __restrict__ Wih,    // [3H][H]
    const float* __restrict__ bih,
    const float* __restrict__ Whh,    // [3H][H]
    const float* __restrict__ bhh,
    float* __restrict__ h_new,        // [H][B]
    float* __restrict__ h1t,          // [B][H] or null
    float* __restrict__ enc_out)      // [B][H] (pre-offset) or null
{
    extern __shared__ float Xd[];
    #define XL(s,h,kk,b) Xd[(((s)*2+(h))*64+(kk))*36+(b)]
    __shared__ float R[4][6][32];
    int tid = threadIdx.x, w = tid >> 5, lane = tid & 31;
    int p = w & 3, hf = w >> 2;
    int j = blockIdx.x*4 + p;
    const float* wxr = Wih + (size_t)j*HSZ          + hf*512;
    const float* wxz = Wih + (size_t)(HSZ+j)*HSZ    + hf*512;
    const float* wxn = Wih + (size_t)(2*HSZ+j)*HSZ  + hf*512;
    const float* whr = Whh + (size_t)j*HSZ          + hf*512;
    const float* whz = Whh + (size_t)(HSZ+j)*HSZ    + hf*512;
    const float* whn = Whh + (size_t)(2*HSZ+j)*HSZ  + hf*512;
    float xr=0.f,xz=0.f,xn=0.f, hr=0.f,hz=0.f,hn=0.f;

    for (int i = 0; i < 8; i++) {
        __syncthreads();
        #pragma unroll
        for (int it = 0; it < 8; it++) {
            int r = (tid >> 3) + it*32;           // 0..255
            int src = r >> 7, rr = r & 127;
            int h = rr >> 6, kk = rr & 63;
            int gk = h*512 + i*64 + kk;
            const float* s = src ? h1o : x0;
            *(float4*)&XL(src, h, kk, (tid & 7)*4) =
                *(const float4*)(s + (size_t)gk*BSZ + (tid & 7)*4);
        }
        __syncthreads();
        #pragma unroll
        for (int q = 0; q < 16; q++) {
            float4 a4 = *(const float4*)(wxr + i*64 + q*4);
            float4 b4 = *(const float4*)(wxz + i*64 + q*4);
            float4 c4 = *(const float4*)(wxn + i*64 + q*4);
            float4 d4 = *(const float4*)(whr + i*64 + q*4);
            float4 e4 = *(const float4*)(whz + i*64 + q*4);
            float4 f4 = *(const float4*)(whn + i*64 + q*4);
            float u0 = XL(0,hf,q*4+0,lane), u1 = XL(0,hf,q*4+1,lane);
            float u2 = XL(0,hf,q*4+2,lane), u3 = XL(0,hf,q*4+3,lane);
            float v0 = XL(1,hf,q*4+0,lane), v1 = XL(1,hf,q*4+1,lane);
            float v2 = XL(1,hf,q*4+2,lane), v3 = XL(1,hf,q*4+3,lane);
            xr += a4.x*u0 + a4.y*u1 + a4.z*u2 + a4.w*u3;
            xz += b4.x*u0 + b4.y*u1 + b4.z*u2 + b4.w*u3;
            xn += c4.x*u0 + c4.y*u1 + c4.z*u2 + c4.w*u3;
            hr += d4.x*v0 + d4.y*v1 + d4.z*v2 + d4.w*v3;
            hz += e4.x*v0 + e4.y*v1 + e4.z*v2 + e4.w*v3;
            hn += f4.x*v0 + f4.y*v1 + f4.z*v2 + f4.w*v3;
        }
    }
    if (hf == 1) {
        R[p][0][lane]=xr; R[p][1][lane]=xz; R[p][2][lane]=xn;
        R[p][3][lane]=hr; R[p][4][lane]=hz; R[p][5][lane]=hn;
    }
    __syncthreads();
    if (hf == 0) {
        float txr = xr + R[p][0][lane] + bih[j];
        float txz = xz + R[p][1][lane] + bih[HSZ+j];
        float txn = xn + R[p][2][lane] + bih[2*HSZ+j];
        float thr = hr + R[p][3][lane] + bhh[j];
        float thz = hz + R[p][4][lane] + bhh[HSZ+j];
        float thn = hn + R[p][5][lane] + bhh[2*HSZ+j];
        float r = 1.f/(1.f + expf(-(txr + thr)));
        float z = 1.f/(1.f + expf(-(txz + thz)));
        float n = tanhf(txn + r*thn);
        float hp = h1o[(size_t)j*BSZ + lane];
        float h = (1.f - z)*n + z*hp;
        h_new[(size_t)j*BSZ + lane] = h;
        if (h1t)     h1t[(size_t)lane*HSZ + j] = h;
        if (enc_out) enc_out[(size_t)lane*HSZ + j] = h;
    }
}

// ---------------- attention (one block per batch element) ----------------
__global__ __launch_bounds__(256) void attn_kernel(
    const float* __restrict__ h1t,
    const float* __restrict__ enc_out_t,
    const int*   __restrict__ src_tokens,
    float* __restrict__ ctx_t)
{
    int b = blockIdx.x;
    int w = threadIdx.x >> 5, lane = threadIdx.x & 31;
    __shared__ float sc[64];

    float4 q[8];
    #pragma unroll
    for (int c = 0; c < 8; c++)
        q[c] = *(const float4*)(h1t + (size_t)b*HSZ + c*128 + lane*4);

    #pragma unroll
    for (int i = 0; i < 8; i++) {
        int s = w*8 + i;
        const float* e = enc_out_t + ((size_t)s*BSZ + b)*HSZ;
        float acc = 0.f;
        #pragma unroll
        for (int c = 0; c < 8; c++) {
            float4 ev = *(const float4*)(e + c*128 + lane*4);
            acc += q[c].x*ev.x + q[c].y*ev.y + q[c].z*ev.z + q[c].w*ev.w;
        }
        #pragma unroll
        for (int off = 16; off; off >>= 1)
            acc += __shfl_xor_sync(0xffffffffu, acc, off);
        if (lane == 0)
            sc[s] = (src_tokens[s*BSZ + b] != PAD_IDX) ? acc : NEGV;
    }
    __syncthreads();

    if (w == 0) {
        float v0 = sc[lane], v1 = sc[lane+32];
        float m = fmaxf(v0, v1);
        #pragma unroll
        for (int off = 16; off; off >>= 1)
            m = fmaxf(m, __shfl_xor_sync(0xffffffffu, m, off));
        float e0 = expf(v0 - m), e1 = expf(v1 - m);
        float ssum = e0 + e1;
        #pragma unroll
        for (int off = 16; off; off >>= 1)
            ssum += __shfl_xor_sync(0xffffffffu, ssum, off);
        sc[lane]    = e0/ssum;
        sc[lane+32] = e1/ssum;
    }
    __syncthreads();

    float4 a4 = make_float4(0.f, 0.f, 0.f, 0.f);
    for (int s = 0; s < SSZ; s++) {
        float at = sc[s];
        float4 ev = *(const float4*)(enc_out_t + ((size_t)s*BSZ + b)*HSZ + threadIdx.x*4);
        a4.x += at*ev.x; a4.y += at*ev.y; a4.z += at*ev.z; a4.w += at*ev.w;
    }
    *(float4*)(ctx_t + (size_t)b*HSZ + threadIdx.x*4) = a4;
}

// ---------------- cc GEMM (k-split across lanes), stores tf32-rounded ------
template<int NVW, int NBW, int KTOT, int K1, bool DOTANH>
__global__ __launch_bounds__(256) void gemm_kt_kernel(
    const float* __restrict__ X1, const float* __restrict__ X2,
    const float* __restrict__ W,  const float* __restrict__ bias,
    float* __restrict__ out, int ldo)
{
    constexpr int NOUT = NVW*NBW;
    int w = threadIdx.x >> 5, lane = threadIdx.x & 31;
    int vbase = blockIdx.y*(8*NVW) + w*NVW;
    int bbase = blockIdx.x*NBW;

    float acc[NOUT];
    #pragma unroll
    for (int i = 0; i < NOUT; i++) acc[i] = 0.f;

    constexpr int CH = KTOT/128;
    #pragma unroll 2
    for (int c = 0; c < CH; c++) {
        int k = c*128 + lane*4;
        float4 xv[NBW];
        #pragma unroll
        for (int jb = 0; jb < NBW; jb++) {
            const float* src = (k < K1)
                ? (X1 + (size_t)(bbase+jb)*K1 + k)
                : (X2 + (size_t)(bbase+jb)*(KTOT-K1) + (k - K1));
            xv[jb] = *(const float4*)src;
        }
        #pragma unroll
        for (int iv = 0; iv < NVW; iv++) {
            float4 wv = *(const float4*)(W + (size_t)(vbase+iv)*KTOT + k);
            #pragma unroll
            for (int jb = 0; jb < NBW; jb++) {
                acc[iv*NBW + jb] += wv.x*xv[jb].x + wv.y*xv[jb].y
                                  + wv.z*xv[jb].z + wv.w*xv[jb].w;
            }
        }
    }

    __shared__ float red[8][32][33];
    #pragma unroll
    for (int g = 0; g < NOUT; g += 32) {
        __syncwarp();
        #pragma unroll
        for (int i = 0; i < 32; i++)
            red[w][i][lane] = acc[g + i];
        __syncwarp();
        float s = 0.f;
        #pragma unroll
        for (int l = 0; l < 32; l++)
            s += red[w][lane][l];
        int oi = g + lane;
        int vi = oi / NBW, jb = oi % NBW;
        int v = vbase + vi;
        float val = s + bias[v];
        if (DOTANH) val = __uint_as_float(f2tf32(tanhf(val)));
        out[(size_t)(bbase+jb)*ldo + v] = val;
    }
}

// ---------------- logits GEMM via mma.sync tf32 ----------------
#define LG_SMEM ((2*128*36 + 2*256*36)*4)
__global__ __launch_bounds__(256) void logits_mma(
    const float* __restrict__ cc,   // [2048][1024] tf32-rounded
    const float* __restrict__ wo,   // [32000][1024] tf32-rounded
    const float* __restrict__ bo,
    float* __restrict__ out)
{
    extern __shared__ uint32_t sm[];
    uint32_t* As = sm;                    // [2][128][36]
    uint32_t* Bs = sm + 2*128*36;         // [2][256][36]

    int tid = threadIdx.x, w = tid >> 5, lane = tid & 31;
    int g = lane >> 2, t4 = lane & 3;
    int warpM = w & 1, warpN = w >> 1;
    int mb = blockIdx.x * 128;            // cc rows
    int vb = blockIdx.y * 256;            // vocab rows

    const float* Ag = cc + (size_t)mb*HSZ;
    const float* Bg = wo + (size_t)vb*HSZ;
    uint32_t as_s = (uint32_t)__cvta_generic_to_shared(As);
    uint32_t bs_s = (uint32_t)__cvta_generic_to_shared(Bs);

    float acc[4][8][4];
    #pragma unroll
    for (int i = 0; i < 4; i++)
        #pragma unroll
        for (int jj = 0; jj < 8; jj++)
            #pragma unroll
            for (int k = 0; k < 4; k++) acc[i][jj][k] = 0.f;

    {
        int kc0 = 0;
        #pragma unroll
        for (int i = 0; i < 4; i++) {
            int idx = tid + i*256, r = idx >> 3, c = (idx & 7)*4;
            cp16(as_s + (r*36 + c)*4, Ag + (size_t)r*HSZ + kc0 + c);
        }
        #pragma unroll
        for (int i = 0; i < 8; i++) {
            int idx = tid + i*256, r = idx >> 3, c = (idx & 7)*4;
            cp16(bs_s + (r*36 + c)*4, Bg + (size_t)r*HSZ + kc0 + c);
        }
        CP_COMMIT();
    }

    for (int ch = 0; ch < 32; ch++) {
        if (ch < 31) {
            int kc0 = (ch+1)*32, buf = (ch+1) & 1;
            uint32_t ao = as_s + buf*128*36*4;
            uint32_t bo_s = bs_s + buf*256*36*4;
            #pragma unroll
            for (int i = 0; i < 4; i++) {
                int idx = tid + i*256, r = idx >> 3, c = (idx & 7)*4;
                cp16(ao + (r*36 + c)*4, Ag + (size_t)r*HSZ + kc0 + c);
            }
            #pragma unroll
            for (int i = 0; i < 8; i++) {
                int idx = tid + i*256, r = idx >> 3, c = (idx & 7)*4;
                cp16(bo_s + (r*36 + c)*4, Bg + (size_t)r*HSZ + kc0 + c);
            }
            CP_COMMIT();
            CP_WAIT(1);
        } else {
            CP_WAIT(0);
        }
        __syncthreads();

        int buf = ch & 1;
        const uint32_t* A0 = As + buf*128*36 + (warpM*64 + g)*36;
        const uint32_t* B0 = Bs + buf*256*36 + (warpN*64 + g)*36;

        #pragma unroll
        for (int ks = 0; ks < 4; ks++) {
            uint32_t a[4][4], b[8][2];
            #pragma unroll
            for (int mf = 0; mf < 4; mf++) {
                const uint32_t* ap = A0 + mf*16*36 + ks*8 + t4;
                a[mf][0] = ap[0];
                a[mf][1] = ap[8*36];
                a[mf][2] = ap[4];
                a[mf][3] = ap[8*36 + 4];
            }
            #pragma unroll
            for (int nf = 0; nf < 8; nf++) {
                const uint32_t* bp = B0 + nf*8*36 + ks*8 + t4;
                b[nf][0] = bp[0];
                b[nf][1] = bp[4];
            }
            #pragma unroll
            for (int mf = 0; mf < 4; mf++)
                #pragma unroll
                for (int nf = 0; nf < 8; nf++)
                    mma_tf32(acc[mf][nf], a[mf], b[nf]);
        }
        __syncthreads();
    }

    #pragma unroll
    for (int nf = 0; nf < 8; nf++) {
        int v = vb + warpN*64 + nf*8 + t4*2;
        float b0v = bo[v], b1v = bo[v+1];
        #pragma unroll
        for (int mf = 0; mf < 4; mf++) {
            int m_lo = mb + warpM*64 + mf*16 + g;
            int m_hi = m_lo + 8;
            if (m_lo < (TSZ-1)*BSZ) {
                out[(size_t)(m_lo + BSZ)*VSZ + v    ] = acc[mf][nf][0] + b0v;
                out[(size_t)(m_lo + BSZ)*VSZ + v + 1] = acc[mf][nf][1] + b1v;
            }
            if (m_hi < (TSZ-1)*BSZ) {
                out[(size_t)(m_hi + BSZ)*VSZ + v    ] = acc[mf][nf][2] + b0v;
                out[(size_t)(m_hi + BSZ)*VSZ + v + 1] = acc[mf][nf][3] + b1v;
            }
        }
    }
}

// ---------------- host ----------------
extern "C" void kernel_launch(void* const* d_in, const int* in_sizes, int n_in,
                              void* d_out, int out_size) {
    const int*   src_tokens = (const int*)  d_in[0];
    const int*   tgt_tokens = (const int*)  d_in[1];
    const float* enc_emb    = (const float*)d_in[2];
    const float* enc_Wih0   = (const float*)d_in[3];
    const float* enc_Whh0   = (const float*)d_in[4];
    const float* enc_bih0   = (const float*)d_in[5];
    const float* enc_bhh0   = (const float*)d_in[6];
    const float* enc_Wih1   = (const float*)d_in[7];
    const float* enc_Whh1   = (const float*)d_in[8];
    const float* enc_bih1   = (const float*)d_in[9];
    const float* enc_bhh1   = (const float*)d_in[10];
    const float* dec_emb    = (const float*)d_in[11];
    const float* dec_Wih0   = (const float*)d_in[12];
    const float* dec_Whh0   = (const float*)d_in[13];
    const float* dec_bih0   = (const float*)d_in[14];
    const float* dec_bhh0   = (const float*)d_in[15];
    const float* dec_Wih1   = (const float*)d_in[16];
    const float* dec_Whh1   = (const float*)d_in[17];
    const float* dec_bih1   = (const float*)d_in[18];
    const float* dec_bhh1   = (const float*)d_in[19];
    const float* Wc         = (const float*)d_in[20];
    const float* bc         = (const float*)d_in[21];
    const float* Wo         = (const float*)d_in[22];
    const float* bo         = (const float*)d_in[23];
    float* out = (float*)d_out;

    float *emb_src, *emb_dec, *gx_enc, *gx_dec;
    float *enc_out_t, *h0, *h1, *dh0, *dh1, *h1t, *ctx_t, *cc_all, *wo_tf;
    cudaGetSymbolAddress((void**)&emb_src,   g_emb_src);
    cudaGetSymbolAddress((void**)&emb_dec,   g_emb_dec);
    cudaGetSymbolAddress((void**)&gx_enc,    g_gx_enc);
    cudaGetSymbolAddress((void**)&gx_dec,    g_gx_dec);
    cudaGetSymbolAddress((void**)&enc_out_t, g_enc_out_t);
    cudaGetSymbolAddress((void**)&h0,        g_h0);
    cudaGetSymbolAddress((void**)&h1,        g_h1);
    cudaGetSymbolAddress((void**)&dh0,       g_dh0);
    cudaGetSymbolAddress((void**)&dh1,       g_dh1);
    cudaGetSymbolAddress((void**)&h1t,       g_h1t);
    cudaGetSymbolAddress((void**)&ctx_t,     g_ctx_t);
    cudaGetSymbolAddress((void**)&cc_all,    g_cc_all);
    cudaGetSymbolAddress((void**)&wo_tf,     g_wo_tf);

    cudaFuncSetAttribute(gru_l1, cudaFuncAttributeMaxDynamicSharedMemorySize, L1_SMEM);
    cudaFuncSetAttribute(logits_mma, cudaFuncAttributeMaxDynamicSharedMemorySize, LG_SMEM);

    // side streams + events, created once on the (uncaptured) correctness call
    static cudaStream_t s1 = nullptr, s2 = nullptr;
    static cudaEvent_t evF, evP, evJ, evA[2], evB[2], evC[2];
    if (!s1) {
        cudaStreamCreateWithFlags(&s1, cudaStreamNonBlocking);
        cudaStreamCreateWithFlags(&s2, cudaStreamNonBlocking);
        cudaEventCreateWithFlags(&evF, cudaEventDisableTiming);
        cudaEventCreateWithFlags(&evP, cudaEventDisableTiming);
        cudaEventCreateWithFlags(&evJ, cudaEventDisableTiming);
        for (int i = 0; i < 2; i++) {
            cudaEventCreateWithFlags(&evA[i], cudaEventDisableTiming);
            cudaEventCreateWithFlags(&evB[i], cudaEventDisableTiming);
            cudaEventCreateWithFlags(&evC[i], cudaEventDisableTiming);
        }
    }

    // ---- fork s2: decoder-side prep, independent of encoder ----
    cudaEventRecord(evF, 0);
    cudaStreamWaitEvent(s2, evF, 0);
    zero_kernel<<<1024, 256, 0, s2>>>(out, BSZ*VSZ);
    embed_kernel<<<((TSZ-1)*BSZ*ESZ)/256, 256, 0, s2>>>(tgt_tokens, dec_emb, emb_dec, (TSZ-1)*BSZ);
    proj_gemm<<<dim3(32, 48), 256, 0, s2>>>(emb_dec, dec_Wih0, dec_bih0, gx_dec);
    cvt_tf32_kernel<<<(VSZ*HSZ/4)/256, 256, 0, s2>>>(Wo, wo_tf);
    cudaEventRecord(evP, s2);

    // ---- s0: encoder prep ----
    zero_h2_kernel<<<(2*HB)/256, 256>>>(h0, h1);
    embed_kernel<<<(SSZ*BSZ*ESZ)/256, 256>>>(src_tokens, enc_emb, emb_src, SSZ*BSZ);
    proj_gemm<<<dim3(32, 48), 256>>>(emb_src, enc_Wih0, enc_bih0, gx_enc);

    // ---- encoder: l0 chain on s0, l1 chain on s1 (overlapped) ----
    for (int t = 0; t < SSZ; t++) {
        int rp = t & 1, wp = rp ^ 1;
        // throttle: l0(t) rewrites parity wp read by l1(t-2); wait for l1(t-2)
        if (t >= 2) cudaStreamWaitEvent(0, evB[t & 1], 0);
        gru_l0<<<256, 256>>>(gx_enc + (size_t)t*3*HSZ*BSZ,
                             h0 + rp*HB, enc_Whh0, enc_bhh0, h0 + wp*HB);
        cudaEventRecord(evA[t & 1], 0);
        cudaStreamWaitEvent(s1, evA[t & 1], 0);
        gru_l1<<<256, 256, L1_SMEM, s1>>>(h0 + wp*HB, h1 + rp*HB,
                             enc_Wih1, enc_bih1, enc_Whh1, enc_bhh1,
                             h1 + wp*HB, nullptr,
                             enc_out_t + (size_t)t*BSZ*HSZ);
        cudaEventRecord(evB[t & 1], s1);
    }
    // S even -> final encoder hidden at parity 0 (h0+0 on s0, h1+0 on s1)

    // ---- decoder ----
    cudaStreamWaitEvent(0, evP, 0);   // gx_dec ready
    for (int t = 0; t < TSZ-1; t++) {
        int wp = (t+1) & 1, rp = t & 1;
        const float* h0r = (t == 0) ? h0 : dh0 + rp*HB;
        const float* h1r = (t == 0) ? h1 : dh1 + rp*HB;
        float* h1tb = h1t + (size_t)(t & 1)*BSZ*HSZ;

        if (t >= 2) cudaStreamWaitEvent(0, evB[t & 1], 0);
        gru_l0<<<256, 256>>>(gx_dec + (size_t)t*3*HSZ*BSZ,
                             h0r, dec_Whh0, dec_bhh0, dh0 + wp*HB);
        cudaEventRecord(evA[t & 1], 0);
        cudaStreamWaitEvent(s1, evA[t & 1], 0);
        if (t >= 2) cudaStreamWaitEvent(s1, evC[t & 1], 0);  // h1t buf free
        gru_l1<<<256, 256, L1_SMEM, s1>>>(dh0 + wp*HB, h1r,
                             dec_Wih1, dec_bih1, dec_Whh1, dec_bhh1,
                             dh1 + wp*HB, h1tb, nullptr);
        cudaEventRecord(evB[t & 1], s1);

        cudaStreamWaitEvent(s2, evB[t & 1], 0);
        attn_kernel<<<BSZ, 256, 0, s2>>>(h1tb, enc_out_t, src_tokens, ctx_t);
        gemm_kt_kernel<4, 8, 2*HSZ, HSZ, true><<<dim3(4, 32), 256, 0, s2>>>(
            h1tb, ctx_t, Wc, bc, cc_all + (size_t)t*BSZ*HSZ, HSZ);
        cudaEventRecord(evC[t & 1], s2);
    }

    // ---- logits on s2 (after all cc writes; wo_tf/out-zero are s2-serial) ----
    logits_mma<<<dim3(16, 125), 256, LG_SMEM, s2>>>(cc_all, wo_tf, bo, out);
    cudaEventRecord(evJ, s2);
    cudaStreamWaitEvent(0, evJ, 0);   // join everything back to the capture stream
}

// round 9
// speedup vs baseline: 1.3155x; 1.3155x over previous
#include <cuda_runtime.h>
#include <math.h>
#include <stdint.h>

#define VSZ 32000
#define ESZ 512
#define HSZ 1024
#define SSZ 64
#define TSZ 64
#define BSZ 32
#define HB  (HSZ*BSZ)          // 32768
#define GXS (3*HSZ*BSZ)        // per-step gx stride
#define PAD_IDX 1
#define NEGV -100000.0f
#define NBLK 256               // persistent grid size

// ---------------- device scratch ----------------
__device__ float g_emb_src[SSZ*BSZ*ESZ];
__device__ float g_emb_dec[TSZ*BSZ*ESZ];
__device__ float g_gx_enc[SSZ*GXS];
__device__ float g_gx_dec[TSZ*GXS];
__device__ float g_enc_out_t[SSZ*BSZ*HSZ];      // [s][b][h]
__device__ float g_h0[2*HB];
__device__ float g_h1[2*HB];
__device__ float g_dh0[2*HB];
__device__ float g_dh1[2*HB];
__device__ float g_h1_all[TSZ*BSZ*HSZ];         // [m=(t,b)][h], tf32-rounded
__device__ float g_ctx_all[TSZ*BSZ*HSZ];        // [m][h], tf32-rounded
__device__ float g_cc_all[TSZ*BSZ*HSZ];         // [m][h], tf32-rounded
__device__ float g_wo_tf[VSZ*HSZ];
__device__ float g_wc_tf[HSZ*2*HSZ];
__device__ int           g_bar_cnt;
__device__ volatile int  g_bar_sense;

// ---------------- helpers ----------------
__device__ __forceinline__ uint32_t f2tf32(float f) {
    uint32_t u;
    asm("cvt.rna.tf32.f32 %0, %1;" : "=r"(u) : "f"(f));
    return u;
}
__device__ __forceinline__ void cp16(uint32_t s, const void* g) {
    asm volatile("cp.async.cg.shared.global [%0], [%1], 16;" :: "r"(s), "l"(g));
}
#define CP_COMMIT() asm volatile("cp.async.commit_group;" ::: "memory")
#define CP_WAIT(N)  asm volatile("cp.async.wait_group %0;" :: "n"(N) : "memory")

__device__ __forceinline__ void mma_tf32(float* c, const uint32_t* a, const uint32_t* b) {
    asm volatile(
        "mma.sync.aligned.m16n8k8.row.col.f32.tf32.tf32.f32 "
        "{%0,%1,%2,%3},{%4,%5,%6,%7},{%8,%9},{%0,%1,%2,%3};"
        : "+f"(c[0]), "+f"(c[1]), "+f"(c[2]), "+f"(c[3])
        : "r"(a[0]), "r"(a[1]), "r"(a[2]), "r"(a[3]), "r"(b[0]), "r"(b[1]));
}

// global barrier (sense-reversing); all NBLK blocks must be resident
__device__ __forceinline__ void gbar(int* sense) {
    __syncthreads();
    if (threadIdx.x == 0) {
        __threadfence();
        int s = (*sense ^= 1);
        if (atomicAdd(&g_bar_cnt, 1) == NBLK - 1) {
            atomicExch(&g_bar_cnt, 0);
            __threadfence();
            g_bar_sense = s;
        } else {
            while (g_bar_sense != s) __nanosleep(32);
        }
    }
    __syncthreads();
}

// ---------------- utility kernels ----------------
__global__ void zero_kernel(float* p, int n) {
    for (int i = blockIdx.x*blockDim.x + threadIdx.x; i < n; i += gridDim.x*blockDim.x)
        p[i] = 0.f;
}
__global__ void zero_h2_kernel(float* a, float* b) {
    int i = blockIdx.x*256 + threadIdx.x;
    if (i < HB) a[i] = 0.f; else b[i - HB] = 0.f;
}
__global__ void cvt_tf32_kernel(const float* __restrict__ in, float* __restrict__ out) {
    int i = blockIdx.x*256 + threadIdx.x;
    float4 v = ((const float4*)in)[i];
    uint4 u = make_uint4(f2tf32(v.x), f2tf32(v.y), f2tf32(v.z), f2tf32(v.w));
    ((uint4*)out)[i] = u;
}
__global__ void embed_kernel(const int* __restrict__ tok,
                             const float* __restrict__ emb,
                             float* __restrict__ out, int rows) {
    int idx = blockIdx.x*256 + threadIdx.x;
    if (idx >= rows*ESZ) return;
    int e = idx & (ESZ-1);
    int m = idx >> 9;
    out[idx] = emb[(size_t)tok[m]*ESZ + e];
}

// ---------------- input projection ----------------
__global__ __launch_bounds__(256) void proj_gemm(
    const float* __restrict__ X, const float* __restrict__ W,
    const float* __restrict__ bih, float* __restrict__ gx)
{
    __shared__ float Xs[2][16][64];
    __shared__ float Ws[2][16][64];
    int tid = threadIdx.x;
    int mb = blockIdx.x*64, nb = blockIdx.y*64;
    int lr = tid >> 2, lc = (tid & 3) * 4;
    const float* Xg = X + (size_t)(mb+lr)*ESZ + lc;
    const float* Wg = W + (size_t)(nb+lr)*ESZ + lc;
    int tm = (tid & 15) * 4, tn = (tid >> 4) * 4;

    float acc[16];
    #pragma unroll
    for (int i = 0; i < 16; i++) acc[i] = 0.f;

    float4 px = *(const float4*)Xg;
    float4 pw = *(const float4*)Wg;
    for (int c = 0; c < 32; c++) {
        int buf = c & 1;
        Xs[buf][lc+0][lr]=px.x; Xs[buf][lc+1][lr]=px.y; Xs[buf][lc+2][lr]=px.z; Xs[buf][lc+3][lr]=px.w;
        Ws[buf][lc+0][lr]=pw.x; Ws[buf][lc+1][lr]=pw.y; Ws[buf][lc+2][lr]=pw.z; Ws[buf][lc+3][lr]=pw.w;
        __syncthreads();
        if (c < 31) {
            px = *(const float4*)(Xg + (c+1)*16);
            pw = *(const float4*)(Wg + (c+1)*16);
        }
        #pragma unroll
        for (int kk = 0; kk < 16; kk++) {
            float4 av = *(const float4*)&Xs[buf][kk][tm];
            float4 wv = *(const float4*)&Ws[buf][kk][tn];
            acc[0]+=av.x*wv.x; acc[1]+=av.x*wv.y; acc[2]+=av.x*wv.z; acc[3]+=av.x*wv.w;
            acc[4]+=av.y*wv.x; acc[5]+=av.y*wv.y; acc[6]+=av.y*wv.z; acc[7]+=av.y*wv.w;
            acc[8]+=av.z*wv.x; acc[9]+=av.z*wv.y; acc[10]+=av.z*wv.z; acc[11]+=av.z*wv.w;
            acc[12]+=av.w*wv.x; acc[13]+=av.w*wv.y; acc[14]+=av.w*wv.z; acc[15]+=av.w*wv.w;
        }
        __syncthreads();
    }
    #pragma unroll
    for (int i = 0; i < 4; i++) {
        int m = mb + tm + i;
        int t = m >> 5, b = m & 31;
        #pragma unroll
        for (int j = 0; j < 4; j++) {
            int n = nb + tn + j;
            gx[(size_t)t*GXS + (size_t)n*BSZ + b] = acc[i*4+j] + bih[n];
        }
    }
}

// ---------------- persistent RNN: phase bodies ----------------
__device__ void l0_phase(float* Xd, const float* gx, const float* h_old,
                         const float* __restrict__ Whh, const float* __restrict__ bhh,
                         float* h_new, int tid, int lane, int p, int hf, int j)
{
    __shared__ float R0[4][3][32];
    const float* wr = Whh + (size_t)j*HSZ          + hf*512;
    const float* wz = Whh + (size_t)(HSZ+j)*HSZ    + hf*512;
    const float* wn = Whh + (size_t)(2*HSZ+j)*HSZ  + hf*512;
    float ar=0.f, az=0.f, an=0.f;

    for (int i = 0; i < 4; i++) {
        __syncthreads();
        #pragma unroll
        for (int it = 0; it < 8; it++) {
            int r = (tid >> 3) + it*32;
            int h = r >> 7, kk = r & 127;
            int gk = h*512 + i*128 + kk;
            float4 v = __ldcg((const float4*)(h_old + (size_t)gk*BSZ + (tid & 7)*4));
            *(float4*)&Xd[(h*128 + kk)*36 + (tid & 7)*4] = v;
        }
        __syncthreads();
        #pragma unroll
        for (int q = 0; q < 32; q++) {
            float4 r4 = *(const float4*)(wr + i*128 + q*4);
            float4 z4 = *(const float4*)(wz + i*128 + q*4);
            float4 n4 = *(const float4*)(wn + i*128 + q*4);
            float x0 = Xd[(hf*128 + q*4+0)*36 + lane], x1 = Xd[(hf*128 + q*4+1)*36 + lane];
            float x2 = Xd[(hf*128 + q*4+2)*36 + lane], x3 = Xd[(hf*128 + q*4+3)*36 + lane];
            ar += r4.x*x0 + r4.y*x1 + r4.z*x2 + r4.w*x3;
            az += z4.x*x0 + z4.y*x1 + z4.z*x2 + z4.w*x3;
            an += n4.x*x0 + n4.y*x1 + n4.z*x2 + n4.w*x3;
        }
    }
    if (hf == 1) { R0[p][0][lane]=ar; R0[p][1][lane]=az; R0[p][2][lane]=an; }
    __syncthreads();
    if (hf == 0) {
        float ghr = ar + R0[p][0][lane] + bhh[j];
        float ghz = az + R0[p][1][lane] + bhh[HSZ+j];
        float ghn = an + R0[p][2][lane] + bhh[2*HSZ+j];
        float gr = gx[(size_t)j*BSZ + lane]       + ghr;
        float gz = gx[(size_t)(HSZ+j)*BSZ + lane] + ghz;
        float r = 1.f/(1.f + expf(-gr));
        float z = 1.f/(1.f + expf(-gz));
        float n = tanhf(gx[(size_t)(2*HSZ+j)*BSZ + lane] + r*ghn);
        float hp = __ldcg(h_old + (size_t)j*BSZ + lane);
        h_new[(size_t)j*BSZ + lane] = (1.f - z)*n + z*hp;
    }
}

__device__ void l1_phase(float* Xd, const float* x0, const float* h1o,
                         const float* __restrict__ Wih, const float* __restrict__ bih,
                         const float* __restrict__ Whh, const float* __restrict__ bhh,
                         float* h_new, float* dest, bool roundDest,
                         int tid, int lane, int p, int hf, int j)
{
    #define XL(s,h,kk,b) Xd[(((s)*2+(h))*64+(kk))*36+(b)]
    __shared__ float R1[4][6][32];
    const float* wxr = Wih + (size_t)j*HSZ          + hf*512;
    const float* wxz = Wih + (size_t)(HSZ+j)*HSZ    + hf*512;
    const float* wxn = Wih + (size_t)(2*HSZ+j)*HSZ  + hf*512;
    const float* whr = Whh + (size_t)j*HSZ          + hf*512;
    const float* whz = Whh + (size_t)(HSZ+j)*HSZ    + hf*512;
    const float* whn = Whh + (size_t)(2*HSZ+j)*HSZ  + hf*512;
    float xr=0.f,xz=0.f,xn=0.f, hr=0.f,hz=0.f,hn=0.f;

    for (int i = 0; i < 8; i++) {
        __syncthreads();
        #pragma unroll
        for (int it = 0; it < 8; it++) {
            int r = (tid >> 3) + it*32;
            int src = r >> 7, rr = r & 127;
            int h = rr >> 6, kk = rr & 63;
            int gk = h*512 + i*64 + kk;
            const float* s = src ? h1o : x0;
            float4 v = __ldcg((const float4*)(s + (size_t)gk*BSZ + (tid & 7)*4));
            *(float4*)&XL(src, h, kk, (tid & 7)*4) = v;
        }
        __syncthreads();
        #pragma unroll
        for (int q = 0; q < 16; q++) {
            float4 a4 = *(const float4*)(wxr + i*64 + q*4);
            float4 b4 = *(const float4*)(wxz + i*64 + q*4);
            float4 c4 = *(const float4*)(wxn + i*64 + q*4);
            float4 d4 = *(const float4*)(whr + i*64 + q*4);
            float4 e4 = *(const float4*)(whz + i*64 + q*4);
            float4 f4 = *(const float4*)(whn + i*64 + q*4);
            float u0 = XL(0,hf,q*4+0,lane), u1 = XL(0,hf,q*4+1,lane);
            float u2 = XL(0,hf,q*4+2,lane), u3 = XL(0,hf,q*4+3,lane);
            float v0 = XL(1,hf,q*4+0,lane), v1 = XL(1,hf,q*4+1,lane);
            float v2 = XL(1,hf,q*4+2,lane), v3 = XL(1,hf,q*4+3,lane);
            xr += a4.x*u0 + a4.y*u1 + a4.z*u2 + a4.w*u3;
            xz += b4.x*u0 + b4.y*u1 + b4.z*u2 + b4.w*u3;
            xn += c4.x*u0 + c4.y*u1 + c4.z*u2 + c4.w*u3;
            hr += d4.x*v0 + d4.y*v1 + d4.z*v2 + d4.w*v3;
            hz += e4.x*v0 + e4.y*v1 + e4.z*v2 + e4.w*v3;
            hn += f4.x*v0 + f4.y*v1 + f4.z*v2 + f4.w*v3;
        }
    }
    if (hf == 1) {
        R1[p][0][lane]=xr; R1[p][1][lane]=xz; R1[p][2][lane]=xn;
        R1[p][3][lane]=hr; R1[p][4][lane]=hz; R1[p][5][lane]=hn;
    }
    __syncthreads();
    if (hf == 0) {
        float txr = xr + R1[p][0][lane] + bih[j];
        float txz = xz + R1[p][1][lane] + bih[HSZ+j];
        float txn = xn + R1[p][2][lane] + bih[2*HSZ+j];
        float thr = hr + R1[p][3][lane] + bhh[j];
        float thz = hz + R1[p][4][lane] + bhh[HSZ+j];
        float thn = hn + R1[p][5][lane] + bhh[2*HSZ+j];
        float r = 1.f/(1.f + expf(-(txr + thr)));
        float z = 1.f/(1.f + expf(-(txz + thz)));
        float n = tanhf(txn + r*thn);
        float hp = __ldcg(h1o + (size_t)j*BSZ + lane);
        float h = (1.f - z)*n + z*hp;
        h_new[(size_t)j*BSZ + lane] = h;
        float hd = roundDest ? __uint_as_float(f2tf32(h)) : h;
        dest[(size_t)lane*HSZ + j] = hd;
    }
    #undef XL
}

#define RNN_SMEM (2*2*64*36*4)  // 73728 B
__global__ __launch_bounds__(256, 2) void rnn_persistent(
    const float* gx_enc, const float* gx_dec,
    const float* eWhh0, const float* ebhh0,
    const float* eWih1, const float* ebih1,
    const float* eWhh1, const float* ebhh1,
    const float* dWhh0, const float* dbhh0,
    const float* dWih1, const float* dbih1,
    const float* dWhh1, const float* dbhh1,
    float* h0, float* h1, float* dh0, float* dh1,
    float* enc_out_t, float* h1_all)
{
    extern __shared__ float Xd[];
    int tid = threadIdx.x, w = tid >> 5, lane = tid & 31;
    int p = w & 3, hf = w >> 2;
    int j = blockIdx.x*4 + p;
    int sense = 0;

    // ---- encoder ----
    for (int t = 0; t < SSZ; t++) {
        int rp = t & 1, wp = rp ^ 1;
        l0_phase(Xd, gx_enc + (size_t)t*GXS, h0 + rp*HB, eWhh0, ebhh0,
                 h0 + wp*HB, tid, lane, p, hf, j);
        gbar(&sense);
        l1_phase(Xd, h0 + wp*HB, h1 + rp*HB, eWih1, ebih1, eWhh1, ebhh1,
                 h1 + wp*HB, enc_out_t + (size_t)t*BSZ*HSZ, false,
                 tid, lane, p, hf, j);
        gbar(&sense);
    }
    // final encoder hidden at parity 0 (S even)

    // ---- decoder ----
    for (int t = 0; t < TSZ-1; t++) {
        int wp = (t+1) & 1, rp = t & 1;
        const float* h0r = (t == 0) ? h0 : dh0 + rp*HB;
        const float* h1r = (t == 0) ? h1 : dh1 + rp*HB;
        l0_phase(Xd, gx_dec + (size_t)t*GXS, h0r, dWhh0, dbhh0,
                 dh0 + wp*HB, tid, lane, p, hf, j);
        gbar(&sense);
        l1_phase(Xd, dh0 + wp*HB, h1r, dWih1, dbih1, dWhh1, dbhh1,
                 dh1 + wp*HB, h1_all + (size_t)t*BSZ*HSZ, true,
                 tid, lane, p, hf, j);
        gbar(&sense);
    }
}

// ---------------- batched attention: grid (b=32, t=63) ----------------
__global__ __launch_bounds__(256) void attn_batched(
    const float* __restrict__ h1_all,     // [m=(t,b)][H]
    const float* __restrict__ enc_out_t,  // [S][B][H]
    const int*   __restrict__ src_tokens, // [S][B]
    float* __restrict__ ctx_all)          // [m][H], tf32-rounded
{
    int b = blockIdx.x, t = blockIdx.y;
    const float* h1t = h1_all + (size_t)t*BSZ*HSZ;
    float* ctx = ctx_all + (size_t)t*BSZ*HSZ;
    int w = threadIdx.x >> 5, lane = threadIdx.x & 31;
    __shared__ float sc[64];

    float4 q[8];
    #pragma unroll
    for (int c = 0; c < 8; c++)
        q[c] = *(const float4*)(h1t + (size_t)b*HSZ + c*128 + lane*4);

    #pragma unroll
    for (int i = 0; i < 8; i++) {
        int s = w*8 + i;
        const float* e = enc_out_t + ((size_t)s*BSZ + b)*HSZ;
        float acc = 0.f;
        #pragma unroll
        for (int c = 0; c < 8; c++) {
            float4 ev = *(const float4*)(e + c*128 + lane*4);
            acc += q[c].x*ev.x + q[c].y*ev.y + q[c].z*ev.z + q[c].w*ev.w;
        }
        #pragma unroll
        for (int off = 16; off; off >>= 1)
            acc += __shfl_xor_sync(0xffffffffu, acc, off);
        if (lane == 0)
            sc[s] = (src_tokens[s*BSZ + b] != PAD_IDX) ? acc : NEGV;
    }
    __syncthreads();

    if (w == 0) {
        float v0 = sc[lane], v1 = sc[lane+32];
        float m = fmaxf(v0, v1);
        #pragma unroll
        for (int off = 16; off; off >>= 1)
            m = fmaxf(m, __shfl_xor_sync(0xffffffffu, m, off));
        float e0 = expf(v0 - m), e1 = expf(v1 - m);
        float ssum = e0 + e1;
        #pragma unroll
        for (int off = 16; off; off >>= 1)
            ssum += __shfl_xor_sync(0xffffffffu, ssum, off);
        sc[lane]    = e0/ssum;
        sc[lane+32] = e1/ssum;
    }
    __syncthreads();

    float4 a4 = make_float4(0.f, 0.f, 0.f, 0.f);
    for (int s = 0; s < SSZ; s++) {
        float at = sc[s];
        float4 ev = *(const float4*)(enc_out_t + ((size_t)s*BSZ + b)*HSZ + threadIdx.x*4);
        a4.x += at*ev.x; a4.y += at*ev.y; a4.z += at*ev.z; a4.w += at*ev.w;
    }
    uint4 u = make_uint4(f2tf32(a4.x), f2tf32(a4.y), f2tf32(a4.z), f2tf32(a4.w));
    *(uint4*)(ctx + (size_t)b*HSZ + threadIdx.x*4) = u;
}

// ---------------- batched cc GEMM via mma (M=2048, N=1024, K=2048) ----
// cc[m][n] = tf32(tanh([h1_all|ctx_all][m]·Wc[n] + bc[n])); tile 128m x 128n.
#define CC_SMEM ((2*128*36 + 2*128*36)*4)
__global__ __launch_bounds__(256) void cc_mma(
    const float* __restrict__ h1a,   // [2048][1024] tf32 bits
    const float* __restrict__ ctxa,  // [2048][1024] tf32 bits
    const float* __restrict__ wc,    // [1024][2048] tf32 bits
    const float* __restrict__ bc,
    float* __restrict__ cc)          // [2048][1024]
{
    extern __shared__ uint32_t sm[];
    uint32_t* As = sm;                    // [2][128][36]
    uint32_t* Bs = sm + 2*128*36;         // [2][128][36]

    int tid = threadIdx.x, w = tid >> 5, lane = tid & 31;
    int g = lane >> 2, t4 = lane & 3;
    int warpM = w & 1, warpN = w >> 1;    // 2 x 4 warps
    int mb = blockIdx.x * 128, nb = blockIdx.y * 128;

    uint32_t as_s = (uint32_t)__cvta_generic_to_shared(As);
    uint32_t bs_s = (uint32_t)__cvta_generic_to_shared(Bs);

    float acc[4][4][4];
    #pragma unroll
    for (int i = 0; i < 4; i++)
        #pragma unroll
        for (int jj = 0; jj < 4; jj++)
            #pragma unroll
            for (int k = 0; k < 4; k++) acc[i][jj][k] = 0.f;

    auto issue = [&](int ch) {
        int kc0 = ch*32, buf = ch & 1;
        uint32_t ao = as_s + buf*128*36*4;
        uint32_t bo2 = bs_s + buf*128*36*4;
        // A tile: 128 rows x 32 floats = 1024 float4  -> 4 iterations
        #pragma unroll
        for (int i = 0; i < 4; i++) {
            int idx = tid + i*256, r = idx >> 3, c = (idx & 7)*4;
            int k = kc0 + c;
            const float* src = (k < HSZ) ? (h1a + (size_t)(mb+r)*HSZ + k)
                                         : (ctxa + (size_t)(mb+r)*HSZ + (k - HSZ));
            cp16(ao + (r*36 + c)*4, src);
        }
        // B tile: 128 rows x 32 floats = 1024 float4  -> 4 iterations
        #pragma unroll
        for (int i = 0; i < 4; i++) {
            int idx = tid + i*256, r = idx >> 3, c = (idx & 7)*4;
            cp16(bo2 + (r*36 + c)*4, wc + (size_t)(nb+r)*(2*HSZ) + kc0 + c);
        }
        CP_COMMIT();
    };

    issue(0);
    for (int ch = 0; ch < 64; ch++) {
        if (ch < 63) { issue(ch+1); CP_WAIT(1); } else { CP_WAIT(0); }
        __syncthreads();
        int buf = ch & 1;
        const uint32_t* A0 = As + buf*128*36 + (warpM*64 + g)*36;
        const uint32_t* B0 = Bs + buf*128*36 + (warpN*32 + g)*36;
        #pragma unroll
        for (int ks = 0; ks < 4; ks++) {
            uint32_t a[4][4], b[4][2];
            #pragma unroll
            for (int mf = 0; mf < 4; mf++) {
                const uint32_t* ap = A0 + mf*16*36 + ks*8 + t4;
                a[mf][0] = ap[0]; a[mf][1] = ap[8*36]; a[mf][2] = ap[4]; a[mf][3] = ap[8*36+4];
            }
            #pragma unroll
            for (int nf = 0; nf < 4; nf++) {
                const uint32_t* bp = B0 + nf*8*36 + ks*8 + t4;
                b[nf][0] = bp[0]; b[nf][1] = bp[4];
            }
            #pragma unroll
            for (int mf = 0; mf < 4; mf++)
                #pragma unroll
                for (int nf = 0; nf < 4; nf++)
                    mma_tf32(acc[mf][nf], a[mf], b[nf]);
        }
        __syncthreads();
    }

    #pragma unroll
    for (int nf = 0; nf < 4; nf++) {
        int n = nb + warpN*32 + nf*8 + t4*2;
        float b0v = bc[n], b1v = bc[n+1];
        #pragma unroll
        for (int mf = 0; mf < 4; mf++) {
            int m_lo = mb + warpM*64 + mf*16 + g;
            int m_hi = m_lo + 8;
            if (m_lo < (TSZ-1)*BSZ) {
                cc[(size_t)m_lo*HSZ + n  ] = __uint_as_float(f2tf32(tanhf(acc[mf][nf][0] + b0v)));
                cc[(size_t)m_lo*HSZ + n+1] = __uint_as_float(f2tf32(tanhf(acc[mf][nf][1] + b1v)));
            }
            if (m_hi < (TSZ-1)*BSZ) {
                cc[(size_t)m_hi*HSZ + n  ] = __uint_as_float(f2tf32(tanhf(acc[mf][nf][2] + b0v)));
                cc[(size_t)m_hi*HSZ + n+1] = __uint_as_float(f2tf32(tanhf(acc[mf][nf][3] + b1v)));
            }
        }
    }
}

// ---------------- logits GEMM via mma.sync tf32 ----------------
#define LG_SMEM ((2*128*36 + 2*256*36)*4)
__global__ __launch_bounds__(256) void logits_mma(
    const float* __restrict__ cc, const float* __restrict__ wo,
    const float* __restrict__ bo, float* __restrict__ out)
{
    extern __shared__ uint32_t sm[];
    uint32_t* As = sm;
    uint32_t* Bs = sm + 2*128*36;

    int tid = threadIdx.x, w = tid >> 5, lane = tid & 31;
    int g = lane >> 2, t4 = lane & 3;
    int warpM = w & 1, warpN = w >> 1;
    int mb = blockIdx.x * 128, vb = blockIdx.y * 256;

    const float* Ag = cc + (size_t)mb*HSZ;
    const float* Bg = wo + (size_t)vb*HSZ;
    uint32_t as_s = (uint32_t)__cvta_generic_to_shared(As);
    uint32_t bs_s = (uint32_t)__cvta_generic_to_shared(Bs);

    float acc[4][8][4];
    #pragma unroll
    for (int i = 0; i < 4; i++)
        #pragma unroll
        for (int jj = 0; jj < 8; jj++)
            #pragma unroll
            for (int k = 0; k < 4; k++) acc[i][jj][k] = 0.f;

    {
        #pragma unroll
        for (int i = 0; i < 4; i++) {
            int idx = tid + i*256, r = idx >> 3, c = (idx & 7)*4;
            cp16(as_s + (r*36 + c)*4, Ag + (size_t)r*HSZ + c);
        }
        #pragma unroll
        for (int i = 0; i < 8; i++) {
            int idx = tid + i*256, r = idx >> 3, c = (idx & 7)*4;
            cp16(bs_s + (r*36 + c)*4, Bg + (size_t)r*HSZ + c);
        }
        CP_COMMIT();
    }

    for (int ch = 0; ch < 32; ch++) {
        if (ch < 31) {
            int kc0 = (ch+1)*32, buf = (ch+1) & 1;
            uint32_t ao = as_s + buf*128*36*4;
            uint32_t bo_s = bs_s + buf*256*36*4;
            #pragma unroll
            for (int i = 0; i < 4; i++) {
                int idx = tid + i*256, r = idx >> 3, c = (idx & 7)*4;
                cp16(ao + (r*36 + c)*4, Ag + (size_t)r*HSZ + kc0 + c);
            }
            #pragma unroll
            for (int i = 0; i < 8; i++) {
                int idx = tid + i*256, r = idx >> 3, c = (idx & 7)*4;
                cp16(bo_s + (r*36 + c)*4, Bg + (size_t)r*HSZ + kc0 + c);
            }
            CP_COMMIT();
            CP_WAIT(1);
        } else {
            CP_WAIT(0);
        }
        __syncthreads();

        int buf = ch & 1;
        const uint32_t* A0 = As + buf*128*36 + (warpM*64 + g)*36;
        const uint32_t* B0 = Bs + buf*256*36 + (warpN*64 + g)*36;

        #pragma unroll
        for (int ks = 0; ks < 4; ks++) {
            uint32_t a[4][4], b[8][2];
            #pragma unroll
            for (int mf = 0; mf < 4; mf++) {
                const uint32_t* ap = A0 + mf*16*36 + ks*8 + t4;
                a[mf][0] = ap[0]; a[mf][1] = ap[8*36]; a[mf][2] = ap[4]; a[mf][3] = ap[8*36+4];
            }
            #pragma unroll
            for (int nf = 0; nf < 8; nf++) {
                const uint32_t* bp = B0 + nf*8*36 + ks*8 + t4;
                b[nf][0] = bp[0]; b[nf][1] = bp[4];
            }
            #pragma unroll
            for (int mf = 0; mf < 4; mf++)
                #pragma unroll
                for (int nf = 0; nf < 8; nf++)
                    mma_tf32(acc[mf][nf], a[mf], b[nf]);
        }
        __syncthreads();
    }

    #pragma unroll
    for (int nf = 0; nf < 8; nf++) {
        int v = vb + warpN*64 + nf*8 + t4*2;
        float b0v = bo[v], b1v = bo[v+1];
        #pragma unroll
        for (int mf = 0; mf < 4; mf++) {
            int m_lo = mb + warpM*64 + mf*16 + g;
            int m_hi = m_lo + 8;
            if (m_lo < (TSZ-1)*BSZ) {
                out[(size_t)(m_lo + BSZ)*VSZ + v    ] = acc[mf][nf][0] + b0v;
                out[(size_t)(m_lo + BSZ)*VSZ + v + 1] = acc[mf][nf][1] + b1v;
            }
            if (m_hi < (TSZ-1)*BSZ) {
                out[(size_t)(m_hi + BSZ)*VSZ + v    ] = acc[mf][nf][2] + b0v;
                out[(size_t)(m_hi + BSZ)*VSZ + v + 1] = acc[mf][nf][3] + b1v;
            }
        }
    }
}

// ---------------- host ----------------
extern "C" void kernel_launch(void* const* d_in, const int* in_sizes, int n_in,
                              void* d_out, int out_size) {
    const int*   src_tokens = (const int*)  d_in[0];
    const int*   tgt_tokens = (const int*)  d_in[1];
    const float* enc_emb    = (const float*)d_in[2];
    const float* enc_Wih0   = (const float*)d_in[3];
    const float* enc_Whh0   = (const float*)d_in[4];
    const float* enc_bih0   = (const float*)d_in[5];
    const float* enc_bhh0   = (const float*)d_in[6];
    const float* enc_Wih1   = (const float*)d_in[7];
    const float* enc_Whh1   = (const float*)d_in[8];
    const float* enc_bih1   = (const float*)d_in[9];
    const float* enc_bhh1   = (const float*)d_in[10];
    const float* dec_emb    = (const float*)d_in[11];
    const float* dec_Wih0   = (const float*)d_in[12];
    const float* dec_Whh0   = (const float*)d_in[13];
    const float* dec_bih0   = (const float*)d_in[14];
    const float* dec_bhh0   = (const float*)d_in[15];
    const float* dec_Wih1   = (const float*)d_in[16];
    const float* dec_Whh1   = (const float*)d_in[17];
    const float* dec_bih1   = (const float*)d_in[18];
    const float* dec_bhh1   = (const float*)d_in[19];
    const float* Wc         = (const float*)d_in[20];
    const float* bc         = (const float*)d_in[21];
    const float* Wo         = (const float*)d_in[22];
    const float* bo         = (const float*)d_in[23];
    float* out = (float*)d_out;

    float *emb_src, *emb_dec, *gx_enc, *gx_dec, *enc_out_t;
    float *h0, *h1, *dh0, *dh1, *h1_all, *ctx_all, *cc_all, *wo_tf, *wc_tf;
    cudaGetSymbolAddress((void**)&emb_src,   g_emb_src);
    cudaGetSymbolAddress((void**)&emb_dec,   g_emb_dec);
    cudaGetSymbolAddress((void**)&gx_enc,    g_gx_enc);
    cudaGetSymbolAddress((void**)&gx_dec,    g_gx_dec);
    cudaGetSymbolAddress((void**)&enc_out_t, g_enc_out_t);
    cudaGetSymbolAddress((void**)&h0,        g_h0);
    cudaGetSymbolAddress((void**)&h1,        g_h1);
    cudaGetSymbolAddress((void**)&dh0,       g_dh0);
    cudaGetSymbolAddress((void**)&dh1,       g_dh1);
    cudaGetSymbolAddress((void**)&h1_all,    g_h1_all);
    cudaGetSymbolAddress((void**)&ctx_all,   g_ctx_all);
    cudaGetSymbolAddress((void**)&cc_all,    g_cc_all);
    cudaGetSymbolAddress((void**)&wo_tf,     g_wo_tf);
    cudaGetSymbolAddress((void**)&wc_tf,     g_wc_tf);

    cudaFuncSetAttribute(rnn_persistent, cudaFuncAttributeMaxDynamicSharedMemorySize, RNN_SMEM);
    cudaFuncSetAttribute(cc_mma,        cudaFuncAttributeMaxDynamicSharedMemorySize, CC_SMEM);
    cudaFuncSetAttribute(logits_mma,    cudaFuncAttributeMaxDynamicSharedMemorySize, LG_SMEM);

    // prep (single stream; graph is a simple chain)
    zero_kernel<<<1024, 256>>>(out, BSZ*VSZ);
    zero_h2_kernel<<<(2*HB)/256, 256>>>(h0, h1);
    embed_kernel<<<(SSZ*BSZ*ESZ)/256, 256>>>(src_tokens, enc_emb, emb_src, SSZ*BSZ);
    embed_kernel<<<((TSZ-1)*BSZ*ESZ)/256, 256>>>(tgt_tokens, dec_emb, emb_dec, (TSZ-1)*BSZ);
    proj_gemm<<<dim3(32, 48), 256>>>(emb_src, enc_Wih0, enc_bih0, gx_enc);
    proj_gemm<<<dim3(32, 48), 256>>>(emb_dec, dec_Wih0, dec_bih0, gx_dec);
    cvt_tf32_kernel<<<(VSZ*HSZ/4)/256, 256>>>(Wo, wo_tf);
    cvt_tf32_kernel<<<(HSZ*2*HSZ/4)/256, 256>>>(Wc, wc_tf);

    // whole recurrence: ONE launch
    rnn_persistent<<<NBLK, 256, RNN_SMEM>>>(
        gx_enc, gx_dec,
        enc_Whh0, enc_bhh0, enc_Wih1, enc_bih1, enc_Whh1, enc_bhh1,
        dec_Whh0, dec_bhh0, dec_Wih1, dec_bih1, dec_Whh1, dec_bhh1,
        h0, h1, dh0, dh1, enc_out_t, h1_all);

    // batched epilogue
    attn_batched<<<dim3(BSZ, TSZ-1), 256>>>(h1_all, enc_out_t, src_tokens, ctx_all);
    cc_mma<<<dim3(16, 8), 256, CC_SMEM>>>(h1_all, ctx_all, wc_tf, bc, cc_all);
    logits_mma<<<dim3(16, 125), 256, LG_SMEM>>>(cc_all, wo_tf, bo, out);
}